// round 15
// baseline (speedup 1.0000x reference)
#include <cuda_runtime.h>
#include <cstdint>
#include <math.h>

#define D 256
#define MAXN 50048   // 50000 rounded up to 128
#define MAXDEG 80    // Poisson(16) max over 50k nodes ~40; 80 is >10 sigma

// Scratch (allocation-free rule: __device__ globals)
__device__ float g_agg[(size_t)MAXN * D];
__device__ float g_x[(size_t)MAXN * D];
__device__ float g_wt[3 * D * D];            // tf32-rounded W1|W2|Wp
__device__ int   g_cnt[MAXN];
__device__ int2  g_ebuf[(size_t)MAXN * MAXDEG];  // (src, w-bits) per dst bucket

__device__ __forceinline__ unsigned f2tf(float f) {
    unsigned r;
    asm("cvt.rna.tf32.f32 %0, %1;" : "=r"(r) : "f"(f));
    return r;
}
__device__ __forceinline__ float f2tf_f(float f) { return __uint_as_float(f2tf(f)); }

// ---------------------------------------------------------------------------
// Round three weight matrices to tf32 once per launch
// ---------------------------------------------------------------------------
__global__ void round_weights(const float* __restrict__ w1, const float* __restrict__ w2,
                              const float* __restrict__ wp, float* __restrict__ out) {
    int i = blockIdx.x * blockDim.x + threadIdx.x;  // float4 index
    const float* src = (i < 16384) ? w1 : (i < 32768) ? w2 : wp;
    int j = i & 16383;
    float4 v = ((const float4*)src)[j];
    float4 o;
    o.x = f2tf_f(v.x); o.y = f2tf_f(v.y); o.z = f2tf_f(v.z); o.w = f2tf_f(v.w);
    ((float4*)out)[i] = o;
}

// ---------------------------------------------------------------------------
// Bucketed adjacency build: zero counters -> scatter (src, w) into dst buckets
// ---------------------------------------------------------------------------
__global__ void zero_int(int* p, int n) {
    int i = blockIdx.x * blockDim.x + threadIdx.x;
    if (i < n) p[i] = 0;
}

__global__ void fill_bucket(const int* __restrict__ srcI, const int* __restrict__ dstI,
                            const float* __restrict__ ew, int* __restrict__ cnt,
                            int2* __restrict__ ebuf, int nE) {
    int i = blockIdx.x * blockDim.x + threadIdx.x;
    if (i < nE) {
        int d = dstI[i];
        int pos = atomicAdd(&cnt[d], 1);
        if (pos < MAXDEG)
            ebuf[(size_t)d * MAXDEG + pos] = make_int2(srcI[i], __float_as_int(ew[i]));
    }
}

// ---------------------------------------------------------------------------
// Gather: agg[i] = x[i] + sum_e w_e * x[src_e]. One warp per node, no atomics.
// Output rounded to tf32 (GEMM consumes it without in-loop cvt).
// ---------------------------------------------------------------------------
__device__ __forceinline__ void fma4(float4& a, float w, const float4& v) {
    a.x = fmaf(w, v.x, a.x);
    a.y = fmaf(w, v.y, a.y);
    a.z = fmaf(w, v.z, a.z);
    a.w = fmaf(w, v.w, a.w);
}

__global__ __launch_bounds__(256) void gather_agg(const float* __restrict__ x,
                                                  const int* __restrict__ cnt,
                                                  const int2* __restrict__ ebuf,
                                                  float* __restrict__ agg, int n) {
    int warp = (blockIdx.x * blockDim.x + threadIdx.x) >> 5;
    if (warp >= n) return;
    int lane = threadIdx.x & 31;

    const float4* xr = (const float4*)(x + (size_t)warp * D);
    float4 a0 = xr[lane];
    float4 a1 = xr[lane + 32];

    int deg = min(cnt[warp], MAXDEG);
    const int2* bp = ebuf + (size_t)warp * MAXDEG;
    int e = 0;
    for (; e + 2 <= deg; e += 2) {
        int2 e0 = bp[e], e1 = bp[e + 1];
        float w0 = __int_as_float(e0.y), w1 = __int_as_float(e1.y);
        const float4* p0 = (const float4*)(x + (size_t)e0.x * D);
        const float4* p1 = (const float4*)(x + (size_t)e1.x * D);
        float4 v00 = p0[lane], v01 = p0[lane + 32];
        float4 v10 = p1[lane], v11 = p1[lane + 32];
        fma4(a0, w0, v00);
        fma4(a1, w0, v01);
        fma4(a0, w1, v10);
        fma4(a1, w1, v11);
    }
    if (e < deg) {
        int2 e0 = bp[e];
        float w0 = __int_as_float(e0.y);
        const float4* p0 = (const float4*)(x + (size_t)e0.x * D);
        fma4(a0, w0, p0[lane]);
        fma4(a1, w0, p0[lane + 32]);
    }

    a0.x = f2tf_f(a0.x); a0.y = f2tf_f(a0.y); a0.z = f2tf_f(a0.z); a0.w = f2tf_f(a0.w);
    a1.x = f2tf_f(a1.x); a1.y = f2tf_f(a1.y); a1.z = f2tf_f(a1.z); a1.w = f2tf_f(a1.w);

    float4* ar = (float4*)(agg + (size_t)warp * D);
    ar[lane] = a0;
    ar[lane + 32] = a1;
}

// ---------------------------------------------------------------------------
// Fused TF32 GEMM (+bias, optional LayerNorm+GELU epilogue)  [R9 known-good]
// Inputs already tf32-rounded in gmem -> no cvt in mainloop.
// cp.async double-buffered, ONE __syncthreads per k-tile.
// BM=64, BN=256, BK=32; 256 threads; 8 warps as 2(M) x 4(N); m16n8k8 mma.
// ---------------------------------------------------------------------------
__device__ __forceinline__ void mma_tf32(float& d0, float& d1, float& d2, float& d3,
                                         unsigned a0, unsigned a1, unsigned a2, unsigned a3,
                                         unsigned b0, unsigned b1) {
    asm volatile(
        "mma.sync.aligned.m16n8k8.row.col.f32.tf32.tf32.f32 "
        "{%0,%1,%2,%3}, {%4,%5,%6,%7}, {%8,%9}, {%0,%1,%2,%3};"
        : "+f"(d0), "+f"(d1), "+f"(d2), "+f"(d3)
        : "r"(a0), "r"(a1), "r"(a2), "r"(a3), "r"(b0), "r"(b1));
}

__device__ __forceinline__ float gelu_exact(float t) {
    return 0.5f * t * (1.0f + erff(t * 0.70710678118654752f));
}

__device__ __forceinline__ void cp_async16(unsigned int s, const void* g) {
    asm volatile("cp.async.cg.shared.global [%0], [%1], 16;" :: "r"(s), "l"(g));
}
__device__ __forceinline__ void cp_commit() {
    asm volatile("cp.async.commit_group;");
}
template <int N>
__device__ __forceinline__ void cp_wait() {
    asm volatile("cp.async.wait_group %0;" :: "n"(N));
}

#define AS_STRIDE 36   // conflict-free A frag loads (bank = 4g + tig)
#define BS_STRIDE 264  // conflict-free B frag loads (bank = 8k' + g)
#define AS_FLOATS (64 * AS_STRIDE)   // 2304
#define BS_FLOATS (32 * BS_STRIDE)   // 8448
#define RED_FLOATS 512
#define GEMM_SMEM_BYTES ((2 * AS_FLOATS + 2 * BS_FLOATS + RED_FLOATS) * 4)  // 88064

template <bool DO_LN>
__global__ __launch_bounds__(256) void gemm_fused(const float* __restrict__ A,
                                                  const float* __restrict__ B,
                                                  const float* __restrict__ bias,
                                                  const float* __restrict__ gamma,
                                                  const float* __restrict__ beta,
                                                  float* __restrict__ C, int M) {
    extern __shared__ float smem[];
    float* Asm[2] = {smem, smem + AS_FLOATS};
    float* Bsm[2] = {smem + 2 * AS_FLOATS, smem + 2 * AS_FLOATS + BS_FLOATS};
    float* red = smem + 2 * AS_FLOATS + 2 * BS_FLOATS;

    int tid = threadIdx.x;
    int row0 = blockIdx.x * 64;

    int wid = tid >> 5;
    int lane = tid & 31;
    int warpM = wid & 1;   // 2 warps down M (32 rows each)
    int warpN = wid >> 1;  // 4 warps across N (64 cols each)
    int g = lane >> 2;     // 0..7
    int tig = lane & 3;    // 0..3

    // A gmem->smem: 64 rows x 32 k; thread copies 8 floats of one row (2x cp16)
    int aRow = tid >> 2;
    int aOff = (tid & 3) * 8;
    int aRowG = min(row0 + aRow, M - 1);  // clamp; invalid rows masked at store
    const float* Ag = A + (size_t)aRowG * D + aOff;
    unsigned int aS[2];
    aS[0] = (unsigned int)__cvta_generic_to_shared(Asm[0] + aRow * AS_STRIDE + aOff);
    aS[1] = (unsigned int)__cvta_generic_to_shared(Asm[1] + aRow * AS_STRIDE + aOff);

    // B gmem->smem: 32 k-rows x 256 cols; thread copies 8 rows x 4 floats
    int bCol = (tid & 63) * 4;
    int bK0 = tid >> 6;
    const float* Bg = B + (size_t)bK0 * D + bCol;
    unsigned int bS[2];
    bS[0] = (unsigned int)__cvta_generic_to_shared(Bsm[0] + bK0 * BS_STRIDE + bCol);
    bS[1] = (unsigned int)__cvta_generic_to_shared(Bsm[1] + bK0 * BS_STRIDE + bCol);

    float acc[2][8][4];
#pragma unroll
    for (int mt = 0; mt < 2; mt++)
#pragma unroll
        for (int nt = 0; nt < 8; nt++)
#pragma unroll
            for (int c = 0; c < 4; c++) acc[mt][nt][c] = 0.0f;

    // prologue: issue tile 0
    {
        cp_async16(aS[0], Ag);
        cp_async16(aS[0] + 16, Ag + 4);
#pragma unroll
        for (int r = 0; r < 8; r++)
            cp_async16(bS[0] + r * 4 * BS_STRIDE * 4, Bg + (size_t)(r * 4) * D);
        cp_commit();
    }

#pragma unroll
    for (int kt = 0; kt < 8; kt++) {
        cp_wait<0>();
        __syncthreads();  // tile kt landed AND all warps done with tile kt-1

        if (kt + 1 < 8) {  // copy(kt+1) overlaps compute(kt)
            int k0 = (kt + 1) * 32;
            int b = (kt + 1) & 1;
            cp_async16(aS[b], Ag + k0);
            cp_async16(aS[b] + 16, Ag + k0 + 4);
#pragma unroll
            for (int r = 0; r < 8; r++)
                cp_async16(bS[b] + r * 4 * BS_STRIDE * 4, Bg + (size_t)(k0 + r * 4) * D);
            cp_commit();
        }

        const float* Ab = Asm[kt & 1];
        const float* Bb = Bsm[kt & 1];
#pragma unroll
        for (int ks = 0; ks < 4; ks++) {
            int kk = ks * 8;
            unsigned af[2][4];
#pragma unroll
            for (int mt = 0; mt < 2; mt++) {
                int r = warpM * 32 + mt * 16 + g;
                const float* ap = &Ab[r * AS_STRIDE + kk];
                af[mt][0] = __float_as_uint(ap[tig]);
                af[mt][1] = __float_as_uint(ap[8 * AS_STRIDE + tig]);
                af[mt][2] = __float_as_uint(ap[tig + 4]);
                af[mt][3] = __float_as_uint(ap[8 * AS_STRIDE + tig + 4]);
            }
            unsigned bf[8][2];
#pragma unroll
            for (int nt = 0; nt < 8; nt++) {
                int c = warpN * 64 + nt * 8 + g;
                bf[nt][0] = __float_as_uint(Bb[(kk + tig) * BS_STRIDE + c]);
                bf[nt][1] = __float_as_uint(Bb[(kk + tig + 4) * BS_STRIDE + c]);
            }
#pragma unroll
            for (int mt = 0; mt < 2; mt++)
#pragma unroll
                for (int nt = 0; nt < 8; nt++)
                    mma_tf32(acc[mt][nt][0], acc[mt][nt][1], acc[mt][nt][2], acc[mt][nt][3],
                             af[mt][0], af[mt][1], af[mt][2], af[mt][3],
                             bf[nt][0], bf[nt][1]);
        }
    }

    // ---- bias add ----
#pragma unroll
    for (int mt = 0; mt < 2; mt++)
#pragma unroll
        for (int nt = 0; nt < 8; nt++) {
            int col = warpN * 64 + nt * 8 + 2 * tig;
            float2 bb = *(const float2*)(bias + col);
            acc[mt][nt][0] += bb.x;
            acc[mt][nt][1] += bb.y;
            acc[mt][nt][2] += bb.x;
            acc[mt][nt][3] += bb.y;
        }

    if (DO_LN) {
        __syncthreads();
#pragma unroll
        for (int mt = 0; mt < 2; mt++) {
            float s0 = 0.f, q0 = 0.f, s1 = 0.f, q1 = 0.f;
#pragma unroll
            for (int nt = 0; nt < 8; nt++) {
                float a = acc[mt][nt][0], b = acc[mt][nt][1];
                float c = acc[mt][nt][2], d = acc[mt][nt][3];
                s0 += a + b; q0 += a * a + b * b;
                s1 += c + d; q1 += c * c + d * d;
            }
#pragma unroll
            for (int o = 1; o < 4; o <<= 1) {
                s0 += __shfl_xor_sync(0xFFFFFFFFu, s0, o);
                q0 += __shfl_xor_sync(0xFFFFFFFFu, q0, o);
                s1 += __shfl_xor_sync(0xFFFFFFFFu, s1, o);
                q1 += __shfl_xor_sync(0xFFFFFFFFu, q1, o);
            }
            if (tig == 0) {
                int r0 = mt * 16 + g, r1 = r0 + 8;
                red[((warpM * 32 + r0) * 4 + warpN) * 2 + 0] = s0;
                red[((warpM * 32 + r0) * 4 + warpN) * 2 + 1] = q0;
                red[((warpM * 32 + r1) * 4 + warpN) * 2 + 0] = s1;
                red[((warpM * 32 + r1) * 4 + warpN) * 2 + 1] = q1;
            }
        }
        __syncthreads();

#pragma unroll
        for (int mt = 0; mt < 2; mt++) {
            int rl0 = mt * 16 + g, rl1 = rl0 + 8;
            float S0 = 0.f, Q0 = 0.f, S1 = 0.f, Q1 = 0.f;
#pragma unroll
            for (int w = 0; w < 4; w++) {
                S0 += red[((warpM * 32 + rl0) * 4 + w) * 2 + 0];
                Q0 += red[((warpM * 32 + rl0) * 4 + w) * 2 + 1];
                S1 += red[((warpM * 32 + rl1) * 4 + w) * 2 + 0];
                Q1 += red[((warpM * 32 + rl1) * 4 + w) * 2 + 1];
            }
            float mu0 = S0 * (1.0f / D);
            float rs0 = rsqrtf(fmaxf(Q0 * (1.0f / D) - mu0 * mu0, 0.f) + 1e-5f);
            float mu1 = S1 * (1.0f / D);
            float rs1 = rsqrtf(fmaxf(Q1 * (1.0f / D) - mu1 * mu1, 0.f) + 1e-5f);

            int r0 = row0 + warpM * 32 + rl0;
            int r1 = row0 + warpM * 32 + rl1;
#pragma unroll
            for (int nt = 0; nt < 8; nt++) {
                int col = warpN * 64 + nt * 8 + 2 * tig;
                float2 gg = *(const float2*)(gamma + col);
                float2 bb = *(const float2*)(beta + col);
                if (r0 < M) {
                    float t0 = (acc[mt][nt][0] - mu0) * rs0 * gg.x + bb.x;
                    float t1 = (acc[mt][nt][1] - mu0) * rs0 * gg.y + bb.y;
                    float2 o = make_float2(f2tf_f(gelu_exact(t0)), f2tf_f(gelu_exact(t1)));
                    *(float2*)(C + (size_t)r0 * D + col) = o;
                }
                if (r1 < M) {
                    float t2 = (acc[mt][nt][2] - mu1) * rs1 * gg.x + bb.x;
                    float t3 = (acc[mt][nt][3] - mu1) * rs1 * gg.y + bb.y;
                    float2 o = make_float2(f2tf_f(gelu_exact(t2)), f2tf_f(gelu_exact(t3)));
                    *(float2*)(C + (size_t)r1 * D + col) = o;
                }
            }
        }
    } else {
#pragma unroll
        for (int mt = 0; mt < 2; mt++) {
            int r0 = row0 + warpM * 32 + mt * 16 + g;
            int r1 = r0 + 8;
#pragma unroll
            for (int nt = 0; nt < 8; nt++) {
                int col = warpN * 64 + nt * 8 + 2 * tig;
                if (r0 < M) {
                    float2 o = make_float2(acc[mt][nt][0], acc[mt][nt][1]);
                    *(float2*)(C + (size_t)r0 * D + col) = o;
                }
                if (r1 < M) {
                    float2 o = make_float2(acc[mt][nt][2], acc[mt][nt][3]);
                    *(float2*)(C + (size_t)r1 * D + col) = o;
                }
            }
        }
    }
}

// ---------------------------------------------------------------------------
extern "C" void kernel_launch(void* const* d_in, const int* in_sizes, int n_in,
                              void* d_out, int out_size) {
    const float* xin = (const float*)d_in[0];
    const int* srcI  = (const int*)d_in[1];
    const int* dstI  = (const int*)d_in[2];
    const float* ew  = (const float*)d_in[3];
    const float* W1  = (const float*)d_in[4];
    const float* b1  = (const float*)d_in[5];
    const float* g1  = (const float*)d_in[6];
    const float* be1 = (const float*)d_in[7];
    const float* W2  = (const float*)d_in[8];
    const float* b2  = (const float*)d_in[9];
    const float* g2  = (const float*)d_in[10];
    const float* be2 = (const float*)d_in[11];
    const float* Wp  = (const float*)d_in[12];
    const float* bp  = (const float*)d_in[13];

    int n  = in_sizes[0] / D;   // 50000
    int nE = in_sizes[1];       // 800000

    float *agg, *xb, *wt;
    int *cnt;
    int2 *ebuf;
    cudaGetSymbolAddress((void**)&agg, g_agg);
    cudaGetSymbolAddress((void**)&xb, g_x);
    cudaGetSymbolAddress((void**)&wt, g_wt);
    cudaGetSymbolAddress((void**)&cnt, g_cnt);
    cudaGetSymbolAddress((void**)&ebuf, g_ebuf);

    cudaFuncSetAttribute(gemm_fused<true>, cudaFuncAttributeMaxDynamicSharedMemorySize,
                         GEMM_SMEM_BYTES);
    cudaFuncSetAttribute(gemm_fused<false>, cudaFuncAttributeMaxDynamicSharedMemorySize,
                         GEMM_SMEM_BYTES);

    int gmBlocks = (n + 63) / 64;
    int gaBlocks = (n + 7) / 8;
    int eBlocks = (nE + 255) / 256;
    int nBlocks = (n + 255) / 256;

    // ----- One-shot prep: weight rounding + bucketed adjacency build -----
    round_weights<<<(3 * 16384 + 255) / 256, 256>>>(W1, W2, Wp, wt);
    zero_int<<<nBlocks, 256>>>(cnt, n);
    fill_bucket<<<eBlocks, 256>>>(srcI, dstI, ew, cnt, ebuf, nE);

    const float* W1t = wt;
    const float* W2t = wt + D * D;
    const float* Wpt = wt + 2 * D * D;

    // ----- Layer 1 -----
    gather_agg<<<gaBlocks, 256>>>(xin, cnt, ebuf, agg, n);
    gemm_fused<true><<<gmBlocks, 256, GEMM_SMEM_BYTES>>>(agg, W1t, b1, g1, be1, xb, n);

    // ----- Layer 2 -----
    gather_agg<<<gaBlocks, 256>>>(xb, cnt, ebuf, agg, n);
    gemm_fused<true><<<gmBlocks, 256, GEMM_SMEM_BYTES>>>(agg, W2t, b2, g2, be2, xb, n);

    // ----- Output projection -----
    gemm_fused<false><<<gmBlocks, 256, GEMM_SMEM_BYTES>>>(xb, Wpt, bp, nullptr, nullptr,
                                                          (float*)d_out, n);
}

// round 16
// speedup vs baseline: 1.0007x; 1.0007x over previous
#include <cuda_runtime.h>
#include <cstdint>
#include <math.h>

#define D 256
#define MAXN 50048   // 50000 rounded up to 128
#define MAXDEG 80    // Poisson(16) max over 50k nodes ~40; 80 is >10 sigma

// Scratch (allocation-free rule: __device__ globals)
__device__ float g_agg[(size_t)MAXN * D];
__device__ float g_x[(size_t)MAXN * D];
__device__ float g_wt[3 * D * D];            // tf32-rounded W1|W2|Wp
__device__ int   g_cnt[MAXN];
__device__ int2  g_ebuf[(size_t)MAXN * MAXDEG];  // (src, w-bits) per dst bucket

__device__ __forceinline__ unsigned f2tf(float f) {
    unsigned r;
    asm("cvt.rna.tf32.f32 %0, %1;" : "=r"(r) : "f"(f));
    return r;
}
__device__ __forceinline__ float f2tf_f(float f) { return __uint_as_float(f2tf(f)); }

// ---------------------------------------------------------------------------
// Round three weight matrices to tf32 once per launch
// ---------------------------------------------------------------------------
__global__ void round_weights(const float* __restrict__ w1, const float* __restrict__ w2,
                              const float* __restrict__ wp, float* __restrict__ out) {
    int i = blockIdx.x * blockDim.x + threadIdx.x;  // float4 index
    const float* src = (i < 16384) ? w1 : (i < 32768) ? w2 : wp;
    int j = i & 16383;
    float4 v = ((const float4*)src)[j];
    float4 o;
    o.x = f2tf_f(v.x); o.y = f2tf_f(v.y); o.z = f2tf_f(v.z); o.w = f2tf_f(v.w);
    ((float4*)out)[i] = o;
}

// ---------------------------------------------------------------------------
// Bucketed adjacency build: zero counters -> scatter (src, w) into dst buckets
// ---------------------------------------------------------------------------
__global__ void zero_int(int* p, int n) {
    int i = blockIdx.x * blockDim.x + threadIdx.x;
    if (i < n) p[i] = 0;
}

__global__ void fill_bucket(const int* __restrict__ srcI, const int* __restrict__ dstI,
                            const float* __restrict__ ew, int* __restrict__ cnt,
                            int2* __restrict__ ebuf, int nE) {
    int i = blockIdx.x * blockDim.x + threadIdx.x;
    if (i < nE) {
        int d = dstI[i];
        int pos = atomicAdd(&cnt[d], 1);
        if (pos < MAXDEG)
            ebuf[(size_t)d * MAXDEG + pos] = make_int2(srcI[i], __float_as_int(ew[i]));
    }
}

// ---------------------------------------------------------------------------
// Gather: agg[i] = x[i] + sum_e w_e * x[src_e]. One warp per node, no atomics.
// Output rounded to tf32 (GEMM consumes it without in-loop cvt).
// ---------------------------------------------------------------------------
__device__ __forceinline__ void fma4(float4& a, float w, const float4& v) {
    a.x = fmaf(w, v.x, a.x);
    a.y = fmaf(w, v.y, a.y);
    a.z = fmaf(w, v.z, a.z);
    a.w = fmaf(w, v.w, a.w);
}

__global__ __launch_bounds__(256) void gather_agg(const float* __restrict__ x,
                                                  const int* __restrict__ cnt,
                                                  const int2* __restrict__ ebuf,
                                                  float* __restrict__ agg, int n) {
    int warp = (blockIdx.x * blockDim.x + threadIdx.x) >> 5;
    if (warp >= n) return;
    int lane = threadIdx.x & 31;

    const float4* xr = (const float4*)(x + (size_t)warp * D);
    float4 a0 = xr[lane];
    float4 a1 = xr[lane + 32];

    int deg = min(cnt[warp], MAXDEG);
    const int2* bp = ebuf + (size_t)warp * MAXDEG;
    int e = 0;
    for (; e + 2 <= deg; e += 2) {
        int2 e0 = bp[e], e1 = bp[e + 1];
        float w0 = __int_as_float(e0.y), w1 = __int_as_float(e1.y);
        const float4* p0 = (const float4*)(x + (size_t)e0.x * D);
        const float4* p1 = (const float4*)(x + (size_t)e1.x * D);
        float4 v00 = p0[lane], v01 = p0[lane + 32];
        float4 v10 = p1[lane], v11 = p1[lane + 32];
        fma4(a0, w0, v00);
        fma4(a1, w0, v01);
        fma4(a0, w1, v10);
        fma4(a1, w1, v11);
    }
    if (e < deg) {
        int2 e0 = bp[e];
        float w0 = __int_as_float(e0.y);
        const float4* p0 = (const float4*)(x + (size_t)e0.x * D);
        fma4(a0, w0, p0[lane]);
        fma4(a1, w0, p0[lane + 32]);
    }

    a0.x = f2tf_f(a0.x); a0.y = f2tf_f(a0.y); a0.z = f2tf_f(a0.z); a0.w = f2tf_f(a0.w);
    a1.x = f2tf_f(a1.x); a1.y = f2tf_f(a1.y); a1.z = f2tf_f(a1.z); a1.w = f2tf_f(a1.w);

    float4* ar = (float4*)(agg + (size_t)warp * D);
    ar[lane] = a0;
    ar[lane + 32] = a1;
}

// ---------------------------------------------------------------------------
// Fused TF32 GEMM (+bias, optional LayerNorm+GELU epilogue)  [R9 known-good]
// Inputs already tf32-rounded in gmem -> no cvt in mainloop.
// cp.async double-buffered, ONE __syncthreads per k-tile.
// BM=64, BN=256, BK=32; 256 threads; 8 warps as 2(M) x 4(N); m16n8k8 mma.
// ---------------------------------------------------------------------------
__device__ __forceinline__ void mma_tf32(float& d0, float& d1, float& d2, float& d3,
                                         unsigned a0, unsigned a1, unsigned a2, unsigned a3,
                                         unsigned b0, unsigned b1) {
    asm volatile(
        "mma.sync.aligned.m16n8k8.row.col.f32.tf32.tf32.f32 "
        "{%0,%1,%2,%3}, {%4,%5,%6,%7}, {%8,%9}, {%0,%1,%2,%3};"
        : "+f"(d0), "+f"(d1), "+f"(d2), "+f"(d3)
        : "r"(a0), "r"(a1), "r"(a2), "r"(a3), "r"(b0), "r"(b1));
}

__device__ __forceinline__ float gelu_exact(float t) {
    return 0.5f * t * (1.0f + erff(t * 0.70710678118654752f));
}

__device__ __forceinline__ void cp_async16(unsigned int s, const void* g) {
    asm volatile("cp.async.cg.shared.global [%0], [%1], 16;" :: "r"(s), "l"(g));
}
__device__ __forceinline__ void cp_commit() {
    asm volatile("cp.async.commit_group;");
}
template <int N>
__device__ __forceinline__ void cp_wait() {
    asm volatile("cp.async.wait_group %0;" :: "n"(N));
}

#define AS_STRIDE 36   // conflict-free A frag loads (bank = 4g + tig)
#define BS_STRIDE 264  // conflict-free B frag loads (bank = 8k' + g)
#define AS_FLOATS (64 * AS_STRIDE)   // 2304
#define BS_FLOATS (32 * BS_STRIDE)   // 8448
#define RED_FLOATS 512
#define GEMM_SMEM_BYTES ((2 * AS_FLOATS + 2 * BS_FLOATS + RED_FLOATS) * 4)  // 88064

template <bool DO_LN>
__global__ __launch_bounds__(256) void gemm_fused(const float* __restrict__ A,
                                                  const float* __restrict__ B,
                                                  const float* __restrict__ bias,
                                                  const float* __restrict__ gamma,
                                                  const float* __restrict__ beta,
                                                  float* __restrict__ C, int M) {
    extern __shared__ float smem[];
    float* Asm[2] = {smem, smem + AS_FLOATS};
    float* Bsm[2] = {smem + 2 * AS_FLOATS, smem + 2 * AS_FLOATS + BS_FLOATS};
    float* red = smem + 2 * AS_FLOATS + 2 * BS_FLOATS;

    int tid = threadIdx.x;
    int row0 = blockIdx.x * 64;

    int wid = tid >> 5;
    int lane = tid & 31;
    int warpM = wid & 1;   // 2 warps down M (32 rows each)
    int warpN = wid >> 1;  // 4 warps across N (64 cols each)
    int g = lane >> 2;     // 0..7
    int tig = lane & 3;    // 0..3

    // A gmem->smem: 64 rows x 32 k; thread copies 8 floats of one row (2x cp16)
    int aRow = tid >> 2;
    int aOff = (tid & 3) * 8;
    int aRowG = min(row0 + aRow, M - 1);  // clamp; invalid rows masked at store
    const float* Ag = A + (size_t)aRowG * D + aOff;
    unsigned int aS[2];
    aS[0] = (unsigned int)__cvta_generic_to_shared(Asm[0] + aRow * AS_STRIDE + aOff);
    aS[1] = (unsigned int)__cvta_generic_to_shared(Asm[1] + aRow * AS_STRIDE + aOff);

    // B gmem->smem: 32 k-rows x 256 cols; thread copies 8 rows x 4 floats
    int bCol = (tid & 63) * 4;
    int bK0 = tid >> 6;
    const float* Bg = B + (size_t)bK0 * D + bCol;
    unsigned int bS[2];
    bS[0] = (unsigned int)__cvta_generic_to_shared(Bsm[0] + bK0 * BS_STRIDE + bCol);
    bS[1] = (unsigned int)__cvta_generic_to_shared(Bsm[1] + bK0 * BS_STRIDE + bCol);

    float acc[2][8][4];
#pragma unroll
    for (int mt = 0; mt < 2; mt++)
#pragma unroll
        for (int nt = 0; nt < 8; nt++)
#pragma unroll
            for (int c = 0; c < 4; c++) acc[mt][nt][c] = 0.0f;

    // prologue: issue tile 0
    {
        cp_async16(aS[0], Ag);
        cp_async16(aS[0] + 16, Ag + 4);
#pragma unroll
        for (int r = 0; r < 8; r++)
            cp_async16(bS[0] + r * 4 * BS_STRIDE * 4, Bg + (size_t)(r * 4) * D);
        cp_commit();
    }

#pragma unroll
    for (int kt = 0; kt < 8; kt++) {
        cp_wait<0>();
        __syncthreads();  // tile kt landed AND all warps done with tile kt-1

        if (kt + 1 < 8) {  // copy(kt+1) overlaps compute(kt)
            int k0 = (kt + 1) * 32;
            int b = (kt + 1) & 1;
            cp_async16(aS[b], Ag + k0);
            cp_async16(aS[b] + 16, Ag + k0 + 4);
#pragma unroll
            for (int r = 0; r < 8; r++)
                cp_async16(bS[b] + r * 4 * BS_STRIDE * 4, Bg + (size_t)(k0 + r * 4) * D);
            cp_commit();
        }

        const float* Ab = Asm[kt & 1];
        const float* Bb = Bsm[kt & 1];
#pragma unroll
        for (int ks = 0; ks < 4; ks++) {
            int kk = ks * 8;
            unsigned af[2][4];
#pragma unroll
            for (int mt = 0; mt < 2; mt++) {
                int r = warpM * 32 + mt * 16 + g;
                const float* ap = &Ab[r * AS_STRIDE + kk];
                af[mt][0] = __float_as_uint(ap[tig]);
                af[mt][1] = __float_as_uint(ap[8 * AS_STRIDE + tig]);
                af[mt][2] = __float_as_uint(ap[tig + 4]);
                af[mt][3] = __float_as_uint(ap[8 * AS_STRIDE + tig + 4]);
            }
            unsigned bf[8][2];
#pragma unroll
            for (int nt = 0; nt < 8; nt++) {
                int c = warpN * 64 + nt * 8 + g;
                bf[nt][0] = __float_as_uint(Bb[(kk + tig) * BS_STRIDE + c]);
                bf[nt][1] = __float_as_uint(Bb[(kk + tig + 4) * BS_STRIDE + c]);
            }
#pragma unroll
            for (int mt = 0; mt < 2; mt++)
#pragma unroll
                for (int nt = 0; nt < 8; nt++)
                    mma_tf32(acc[mt][nt][0], acc[mt][nt][1], acc[mt][nt][2], acc[mt][nt][3],
                             af[mt][0], af[mt][1], af[mt][2], af[mt][3],
                             bf[nt][0], bf[nt][1]);
        }
    }

    // ---- bias add ----
#pragma unroll
    for (int mt = 0; mt < 2; mt++)
#pragma unroll
        for (int nt = 0; nt < 8; nt++) {
            int col = warpN * 64 + nt * 8 + 2 * tig;
            float2 bb = *(const float2*)(bias + col);
            acc[mt][nt][0] += bb.x;
            acc[mt][nt][1] += bb.y;
            acc[mt][nt][2] += bb.x;
            acc[mt][nt][3] += bb.y;
        }

    if (DO_LN) {
        __syncthreads();
#pragma unroll
        for (int mt = 0; mt < 2; mt++) {
            float s0 = 0.f, q0 = 0.f, s1 = 0.f, q1 = 0.f;
#pragma unroll
            for (int nt = 0; nt < 8; nt++) {
                float a = acc[mt][nt][0], b = acc[mt][nt][1];
                float c = acc[mt][nt][2], d = acc[mt][nt][3];
                s0 += a + b; q0 += a * a + b * b;
                s1 += c + d; q1 += c * c + d * d;
            }
#pragma unroll
            for (int o = 1; o < 4; o <<= 1) {
                s0 += __shfl_xor_sync(0xFFFFFFFFu, s0, o);
                q0 += __shfl_xor_sync(0xFFFFFFFFu, q0, o);
                s1 += __shfl_xor_sync(0xFFFFFFFFu, s1, o);
                q1 += __shfl_xor_sync(0xFFFFFFFFu, q1, o);
            }
            if (tig == 0) {
                int r0 = mt * 16 + g, r1 = r0 + 8;
                red[((warpM * 32 + r0) * 4 + warpN) * 2 + 0] = s0;
                red[((warpM * 32 + r0) * 4 + warpN) * 2 + 1] = q0;
                red[((warpM * 32 + r1) * 4 + warpN) * 2 + 0] = s1;
                red[((warpM * 32 + r1) * 4 + warpN) * 2 + 1] = q1;
            }
        }
        __syncthreads();

#pragma unroll
        for (int mt = 0; mt < 2; mt++) {
            int rl0 = mt * 16 + g, rl1 = rl0 + 8;
            float S0 = 0.f, Q0 = 0.f, S1 = 0.f, Q1 = 0.f;
#pragma unroll
            for (int w = 0; w < 4; w++) {
                S0 += red[((warpM * 32 + rl0) * 4 + w) * 2 + 0];
                Q0 += red[((warpM * 32 + rl0) * 4 + w) * 2 + 1];
                S1 += red[((warpM * 32 + rl1) * 4 + w) * 2 + 0];
                Q1 += red[((warpM * 32 + rl1) * 4 + w) * 2 + 1];
            }
            float mu0 = S0 * (1.0f / D);
            float rs0 = rsqrtf(fmaxf(Q0 * (1.0f / D) - mu0 * mu0, 0.f) + 1e-5f);
            float mu1 = S1 * (1.0f / D);
            float rs1 = rsqrtf(fmaxf(Q1 * (1.0f / D) - mu1 * mu1, 0.f) + 1e-5f);

            int r0 = row0 + warpM * 32 + rl0;
            int r1 = row0 + warpM * 32 + rl1;
#pragma unroll
            for (int nt = 0; nt < 8; nt++) {
                int col = warpN * 64 + nt * 8 + 2 * tig;
                float2 gg = *(const float2*)(gamma + col);
                float2 bb = *(const float2*)(beta + col);
                if (r0 < M) {
                    float t0 = (acc[mt][nt][0] - mu0) * rs0 * gg.x + bb.x;
                    float t1 = (acc[mt][nt][1] - mu0) * rs0 * gg.y + bb.y;
                    float2 o = make_float2(f2tf_f(gelu_exact(t0)), f2tf_f(gelu_exact(t1)));
                    *(float2*)(C + (size_t)r0 * D + col) = o;
                }
                if (r1 < M) {
                    float t2 = (acc[mt][nt][2] - mu1) * rs1 * gg.x + bb.x;
                    float t3 = (acc[mt][nt][3] - mu1) * rs1 * gg.y + bb.y;
                    float2 o = make_float2(f2tf_f(gelu_exact(t2)), f2tf_f(gelu_exact(t3)));
                    *(float2*)(C + (size_t)r1 * D + col) = o;
                }
            }
        }
    } else {
#pragma unroll
        for (int mt = 0; mt < 2; mt++) {
            int r0 = row0 + warpM * 32 + mt * 16 + g;
            int r1 = r0 + 8;
#pragma unroll
            for (int nt = 0; nt < 8; nt++) {
                int col = warpN * 64 + nt * 8 + 2 * tig;
                if (r0 < M) {
                    float2 o = make_float2(acc[mt][nt][0], acc[mt][nt][1]);
                    *(float2*)(C + (size_t)r0 * D + col) = o;
                }
                if (r1 < M) {
                    float2 o = make_float2(acc[mt][nt][2], acc[mt][nt][3]);
                    *(float2*)(C + (size_t)r1 * D + col) = o;
                }
            }
        }
    }
}

// ---------------------------------------------------------------------------
extern "C" void kernel_launch(void* const* d_in, const int* in_sizes, int n_in,
                              void* d_out, int out_size) {
    const float* xin = (const float*)d_in[0];
    const int* srcI  = (const int*)d_in[1];
    const int* dstI  = (const int*)d_in[2];
    const float* ew  = (const float*)d_in[3];
    const float* W1  = (const float*)d_in[4];
    const float* b1  = (const float*)d_in[5];
    const float* g1  = (const float*)d_in[6];
    const float* be1 = (const float*)d_in[7];
    const float* W2  = (const float*)d_in[8];
    const float* b2  = (const float*)d_in[9];
    const float* g2  = (const float*)d_in[10];
    const float* be2 = (const float*)d_in[11];
    const float* Wp  = (const float*)d_in[12];
    const float* bp  = (const float*)d_in[13];

    int n  = in_sizes[0] / D;   // 50000
    int nE = in_sizes[1];       // 800000

    float *agg, *xb, *wt;
    int *cnt;
    int2 *ebuf;
    cudaGetSymbolAddress((void**)&agg, g_agg);
    cudaGetSymbolAddress((void**)&xb, g_x);
    cudaGetSymbolAddress((void**)&wt, g_wt);
    cudaGetSymbolAddress((void**)&cnt, g_cnt);
    cudaGetSymbolAddress((void**)&ebuf, g_ebuf);

    cudaFuncSetAttribute(gemm_fused<true>, cudaFuncAttributeMaxDynamicSharedMemorySize,
                         GEMM_SMEM_BYTES);
    cudaFuncSetAttribute(gemm_fused<false>, cudaFuncAttributeMaxDynamicSharedMemorySize,
                         GEMM_SMEM_BYTES);

    int gmBlocks = (n + 63) / 64;
    int gaBlocks = (n + 7) / 8;
    int eBlocks = (nE + 255) / 256;
    int nBlocks = (n + 255) / 256;

    // ----- One-shot prep: weight rounding + bucketed adjacency build -----
    round_weights<<<(3 * 16384 + 255) / 256, 256>>>(W1, W2, Wp, wt);
    zero_int<<<nBlocks, 256>>>(cnt, n);
    fill_bucket<<<eBlocks, 256>>>(srcI, dstI, ew, cnt, ebuf, nE);

    const float* W1t = wt;
    const float* W2t = wt + D * D;
    const float* Wpt = wt + 2 * D * D;

    // ----- Layer 1 -----
    gather_agg<<<gaBlocks, 256>>>(xin, cnt, ebuf, agg, n);
    gemm_fused<true><<<gmBlocks, 256, GEMM_SMEM_BYTES>>>(agg, W1t, b1, g1, be1, xb, n);

    // ----- Layer 2 -----
    gather_agg<<<gaBlocks, 256>>>(xb, cnt, ebuf, agg, n);
    gemm_fused<true><<<gmBlocks, 256, GEMM_SMEM_BYTES>>>(agg, W2t, b2, g2, be2, xb, n);

    // ----- Output projection -----
    gemm_fused<false><<<gmBlocks, 256, GEMM_SMEM_BYTES>>>(xb, Wpt, bp, nullptr, nullptr,
                                                          (float*)d_out, n);
}

// round 17
// speedup vs baseline: 1.0230x; 1.0222x over previous
#include <cuda_runtime.h>
#include <cstdint>
#include <math.h>

#define D 256
#define MAXN 50048   // 50000 rounded up to 128
#define MAXDEG 80    // Poisson(16) max over 50k nodes ~40; 80 is >10 sigma

// Scratch (allocation-free rule: __device__ globals)
__device__ float g_agg[(size_t)MAXN * D];
__device__ float g_x[(size_t)MAXN * D];
__device__ float g_wt[3 * D * D];            // tf32-rounded W1|W2|Wp
__device__ int   g_cnt[MAXN];
__device__ int2  g_ebuf[(size_t)MAXN * MAXDEG];  // (src, w-bits) per dst bucket

__device__ __forceinline__ unsigned f2tf(float f) {
    unsigned r;
    asm("cvt.rna.tf32.f32 %0, %1;" : "=r"(r) : "f"(f));
    return r;
}
__device__ __forceinline__ float f2tf_f(float f) { return __uint_as_float(f2tf(f)); }

// ---------------------------------------------------------------------------
// Round three weight matrices to tf32 once per launch
// ---------------------------------------------------------------------------
__global__ void round_weights(const float* __restrict__ w1, const float* __restrict__ w2,
                              const float* __restrict__ wp, float* __restrict__ out) {
    int i = blockIdx.x * blockDim.x + threadIdx.x;  // float4 index
    const float* src = (i < 16384) ? w1 : (i < 32768) ? w2 : wp;
    int j = i & 16383;
    float4 v = ((const float4*)src)[j];
    float4 o;
    o.x = f2tf_f(v.x); o.y = f2tf_f(v.y); o.z = f2tf_f(v.z); o.w = f2tf_f(v.w);
    ((float4*)out)[i] = o;
}

// ---------------------------------------------------------------------------
// Bucketed adjacency build: zero counters -> scatter (src, w) into dst buckets
// ---------------------------------------------------------------------------
__global__ void zero_int(int* p, int n) {
    int i = blockIdx.x * blockDim.x + threadIdx.x;
    if (i < n) p[i] = 0;
}

__global__ void fill_bucket(const int* __restrict__ srcI, const int* __restrict__ dstI,
                            const float* __restrict__ ew, int* __restrict__ cnt,
                            int2* __restrict__ ebuf, int nE) {
    int i = blockIdx.x * blockDim.x + threadIdx.x;
    if (i < nE) {
        int d = dstI[i];
        int pos = atomicAdd(&cnt[d], 1);
        if (pos < MAXDEG)
            ebuf[(size_t)d * MAXDEG + pos] = make_int2(srcI[i], __float_as_int(ew[i]));
    }
}

// ---------------------------------------------------------------------------
// Gather: agg[i] = x[i] + sum_e w_e * x[src_e]. One warp per node, no atomics.
// Edge descriptors preloaded lane-parallel and broadcast via shfl -> the loop
// has ZERO dependent edge loads; unroll-4 keeps 8 float4 row loads in flight.
// Output rounded to tf32 (GEMM consumes it without in-loop cvt).
// ---------------------------------------------------------------------------
__device__ __forceinline__ void fma4(float4& a, float w, const float4& v) {
    a.x = fmaf(w, v.x, a.x);
    a.y = fmaf(w, v.y, a.y);
    a.z = fmaf(w, v.z, a.z);
    a.w = fmaf(w, v.w, a.w);
}

__global__ __launch_bounds__(256) void gather_agg(const float* __restrict__ x,
                                                  const int* __restrict__ cnt,
                                                  const int2* __restrict__ ebuf,
                                                  float* __restrict__ agg, int n) {
    int warp = (blockIdx.x * blockDim.x + threadIdx.x) >> 5;
    if (warp >= n) return;
    int lane = threadIdx.x & 31;

    int deg = min(cnt[warp], MAXDEG);
    const int2* bp = ebuf + (size_t)warp * MAXDEG;

    // lane-parallel edge preload (coalesced LDG.64 x3), broadcast later by shfl
    int2 eA = (lane < deg) ? bp[lane] : make_int2(0, 0);
    int2 eB = (lane + 32 < deg) ? bp[lane + 32] : make_int2(0, 0);
    int2 eC = (lane + 64 < deg) ? bp[lane + 64] : make_int2(0, 0);

    const float4* xr = (const float4*)(x + (size_t)warp * D);
    float4 a0 = xr[lane];
    float4 a1 = xr[lane + 32];

#define EDGE_GET(j, sv, wv)                                                   \
    {                                                                         \
        int2 _t = ((j) < 32) ? eA : (((j) < 64) ? eB : eC);                   \
        sv = __shfl_sync(0xFFFFFFFFu, _t.x, (j) & 31);                        \
        wv = __int_as_float(__shfl_sync(0xFFFFFFFFu, _t.y, (j) & 31));        \
    }

    int e = 0;
    for (; e + 4 <= deg; e += 4) {
        int s0, s1, s2, s3;
        float w0, w1, w2, w3;
        EDGE_GET(e + 0, s0, w0);
        EDGE_GET(e + 1, s1, w1);
        EDGE_GET(e + 2, s2, w2);
        EDGE_GET(e + 3, s3, w3);
        const float4* p0 = (const float4*)(x + (size_t)s0 * D);
        const float4* p1 = (const float4*)(x + (size_t)s1 * D);
        const float4* p2 = (const float4*)(x + (size_t)s2 * D);
        const float4* p3 = (const float4*)(x + (size_t)s3 * D);
        float4 v00 = p0[lane], v01 = p0[lane + 32];
        float4 v10 = p1[lane], v11 = p1[lane + 32];
        float4 v20 = p2[lane], v21 = p2[lane + 32];
        float4 v30 = p3[lane], v31 = p3[lane + 32];
        fma4(a0, w0, v00); fma4(a1, w0, v01);
        fma4(a0, w1, v10); fma4(a1, w1, v11);
        fma4(a0, w2, v20); fma4(a1, w2, v21);
        fma4(a0, w3, v30); fma4(a1, w3, v31);
    }
    for (; e < deg; e++) {
        int s0;
        float w0;
        EDGE_GET(e, s0, w0);
        const float4* p0 = (const float4*)(x + (size_t)s0 * D);
        fma4(a0, w0, p0[lane]);
        fma4(a1, w0, p0[lane + 32]);
    }
#undef EDGE_GET

    a0.x = f2tf_f(a0.x); a0.y = f2tf_f(a0.y); a0.z = f2tf_f(a0.z); a0.w = f2tf_f(a0.w);
    a1.x = f2tf_f(a1.x); a1.y = f2tf_f(a1.y); a1.z = f2tf_f(a1.z); a1.w = f2tf_f(a1.w);

    float4* ar = (float4*)(agg + (size_t)warp * D);
    ar[lane] = a0;
    ar[lane + 32] = a1;
}

// ---------------------------------------------------------------------------
// Fused TF32 GEMM (+bias, optional LayerNorm+GELU epilogue)  [R9 known-good]
// Inputs already tf32-rounded in gmem -> no cvt in mainloop.
// cp.async double-buffered, ONE __syncthreads per k-tile.
// BM=64, BN=256, BK=32; 256 threads; 8 warps as 2(M) x 4(N); m16n8k8 mma.
// ---------------------------------------------------------------------------
__device__ __forceinline__ void mma_tf32(float& d0, float& d1, float& d2, float& d3,
                                         unsigned a0, unsigned a1, unsigned a2, unsigned a3,
                                         unsigned b0, unsigned b1) {
    asm volatile(
        "mma.sync.aligned.m16n8k8.row.col.f32.tf32.tf32.f32 "
        "{%0,%1,%2,%3}, {%4,%5,%6,%7}, {%8,%9}, {%0,%1,%2,%3};"
        : "+f"(d0), "+f"(d1), "+f"(d2), "+f"(d3)
        : "r"(a0), "r"(a1), "r"(a2), "r"(a3), "r"(b0), "r"(b1));
}

__device__ __forceinline__ float gelu_exact(float t) {
    return 0.5f * t * (1.0f + erff(t * 0.70710678118654752f));
}

__device__ __forceinline__ void cp_async16(unsigned int s, const void* g) {
    asm volatile("cp.async.cg.shared.global [%0], [%1], 16;" :: "r"(s), "l"(g));
}
__device__ __forceinline__ void cp_commit() {
    asm volatile("cp.async.commit_group;");
}
template <int N>
__device__ __forceinline__ void cp_wait() {
    asm volatile("cp.async.wait_group %0;" :: "n"(N));
}

#define AS_STRIDE 36   // conflict-free A frag loads (bank = 4g + tig)
#define BS_STRIDE 264  // conflict-free B frag loads (bank = 8k' + g)
#define AS_FLOATS (64 * AS_STRIDE)   // 2304
#define BS_FLOATS (32 * BS_STRIDE)   // 8448
#define RED_FLOATS 512
#define GEMM_SMEM_BYTES ((2 * AS_FLOATS + 2 * BS_FLOATS + RED_FLOATS) * 4)  // 88064

template <bool DO_LN>
__global__ __launch_bounds__(256) void gemm_fused(const float* __restrict__ A,
                                                  const float* __restrict__ B,
                                                  const float* __restrict__ bias,
                                                  const float* __restrict__ gamma,
                                                  const float* __restrict__ beta,
                                                  float* __restrict__ C, int M) {
    extern __shared__ float smem[];
    float* Asm[2] = {smem, smem + AS_FLOATS};
    float* Bsm[2] = {smem + 2 * AS_FLOATS, smem + 2 * AS_FLOATS + BS_FLOATS};
    float* red = smem + 2 * AS_FLOATS + 2 * BS_FLOATS;

    int tid = threadIdx.x;
    int row0 = blockIdx.x * 64;

    int wid = tid >> 5;
    int lane = tid & 31;
    int warpM = wid & 1;   // 2 warps down M (32 rows each)
    int warpN = wid >> 1;  // 4 warps across N (64 cols each)
    int g = lane >> 2;     // 0..7
    int tig = lane & 3;    // 0..3

    // A gmem->smem: 64 rows x 32 k; thread copies 8 floats of one row (2x cp16)
    int aRow = tid >> 2;
    int aOff = (tid & 3) * 8;
    int aRowG = min(row0 + aRow, M - 1);  // clamp; invalid rows masked at store
    const float* Ag = A + (size_t)aRowG * D + aOff;
    unsigned int aS[2];
    aS[0] = (unsigned int)__cvta_generic_to_shared(Asm[0] + aRow * AS_STRIDE + aOff);
    aS[1] = (unsigned int)__cvta_generic_to_shared(Asm[1] + aRow * AS_STRIDE + aOff);

    // B gmem->smem: 32 k-rows x 256 cols; thread copies 8 rows x 4 floats
    int bCol = (tid & 63) * 4;
    int bK0 = tid >> 6;
    const float* Bg = B + (size_t)bK0 * D + bCol;
    unsigned int bS[2];
    bS[0] = (unsigned int)__cvta_generic_to_shared(Bsm[0] + bK0 * BS_STRIDE + bCol);
    bS[1] = (unsigned int)__cvta_generic_to_shared(Bsm[1] + bK0 * BS_STRIDE + bCol);

    float acc[2][8][4];
#pragma unroll
    for (int mt = 0; mt < 2; mt++)
#pragma unroll
        for (int nt = 0; nt < 8; nt++)
#pragma unroll
            for (int c = 0; c < 4; c++) acc[mt][nt][c] = 0.0f;

    // prologue: issue tile 0
    {
        cp_async16(aS[0], Ag);
        cp_async16(aS[0] + 16, Ag + 4);
#pragma unroll
        for (int r = 0; r < 8; r++)
            cp_async16(bS[0] + r * 4 * BS_STRIDE * 4, Bg + (size_t)(r * 4) * D);
        cp_commit();
    }

#pragma unroll
    for (int kt = 0; kt < 8; kt++) {
        cp_wait<0>();
        __syncthreads();  // tile kt landed AND all warps done with tile kt-1

        if (kt + 1 < 8) {  // copy(kt+1) overlaps compute(kt)
            int k0 = (kt + 1) * 32;
            int b = (kt + 1) & 1;
            cp_async16(aS[b], Ag + k0);
            cp_async16(aS[b] + 16, Ag + k0 + 4);
#pragma unroll
            for (int r = 0; r < 8; r++)
                cp_async16(bS[b] + r * 4 * BS_STRIDE * 4, Bg + (size_t)(k0 + r * 4) * D);
            cp_commit();
        }

        const float* Ab = Asm[kt & 1];
        const float* Bb = Bsm[kt & 1];
#pragma unroll
        for (int ks = 0; ks < 4; ks++) {
            int kk = ks * 8;
            unsigned af[2][4];
#pragma unroll
            for (int mt = 0; mt < 2; mt++) {
                int r = warpM * 32 + mt * 16 + g;
                const float* ap = &Ab[r * AS_STRIDE + kk];
                af[mt][0] = __float_as_uint(ap[tig]);
                af[mt][1] = __float_as_uint(ap[8 * AS_STRIDE + tig]);
                af[mt][2] = __float_as_uint(ap[tig + 4]);
                af[mt][3] = __float_as_uint(ap[8 * AS_STRIDE + tig + 4]);
            }
            unsigned bf[8][2];
#pragma unroll
            for (int nt = 0; nt < 8; nt++) {
                int c = warpN * 64 + nt * 8 + g;
                bf[nt][0] = __float_as_uint(Bb[(kk + tig) * BS_STRIDE + c]);
                bf[nt][1] = __float_as_uint(Bb[(kk + tig + 4) * BS_STRIDE + c]);
            }
#pragma unroll
            for (int mt = 0; mt < 2; mt++)
#pragma unroll
                for (int nt = 0; nt < 8; nt++)
                    mma_tf32(acc[mt][nt][0], acc[mt][nt][1], acc[mt][nt][2], acc[mt][nt][3],
                             af[mt][0], af[mt][1], af[mt][2], af[mt][3],
                             bf[nt][0], bf[nt][1]);
        }
    }

    // ---- bias add ----
#pragma unroll
    for (int mt = 0; mt < 2; mt++)
#pragma unroll
        for (int nt = 0; nt < 8; nt++) {
            int col = warpN * 64 + nt * 8 + 2 * tig;
            float2 bb = *(const float2*)(bias + col);
            acc[mt][nt][0] += bb.x;
            acc[mt][nt][1] += bb.y;
            acc[mt][nt][2] += bb.x;
            acc[mt][nt][3] += bb.y;
        }

    if (DO_LN) {
        __syncthreads();
#pragma unroll
        for (int mt = 0; mt < 2; mt++) {
            float s0 = 0.f, q0 = 0.f, s1 = 0.f, q1 = 0.f;
#pragma unroll
            for (int nt = 0; nt < 8; nt++) {
                float a = acc[mt][nt][0], b = acc[mt][nt][1];
                float c = acc[mt][nt][2], d = acc[mt][nt][3];
                s0 += a + b; q0 += a * a + b * b;
                s1 += c + d; q1 += c * c + d * d;
            }
#pragma unroll
            for (int o = 1; o < 4; o <<= 1) {
                s0 += __shfl_xor_sync(0xFFFFFFFFu, s0, o);
                q0 += __shfl_xor_sync(0xFFFFFFFFu, q0, o);
                s1 += __shfl_xor_sync(0xFFFFFFFFu, s1, o);
                q1 += __shfl_xor_sync(0xFFFFFFFFu, q1, o);
            }
            if (tig == 0) {
                int r0 = mt * 16 + g, r1 = r0 + 8;
                red[((warpM * 32 + r0) * 4 + warpN) * 2 + 0] = s0;
                red[((warpM * 32 + r0) * 4 + warpN) * 2 + 1] = q0;
                red[((warpM * 32 + r1) * 4 + warpN) * 2 + 0] = s1;
                red[((warpM * 32 + r1) * 4 + warpN) * 2 + 1] = q1;
            }
        }
        __syncthreads();

#pragma unroll
        for (int mt = 0; mt < 2; mt++) {
            int rl0 = mt * 16 + g, rl1 = rl0 + 8;
            float S0 = 0.f, Q0 = 0.f, S1 = 0.f, Q1 = 0.f;
#pragma unroll
            for (int w = 0; w < 4; w++) {
                S0 += red[((warpM * 32 + rl0) * 4 + w) * 2 + 0];
                Q0 += red[((warpM * 32 + rl0) * 4 + w) * 2 + 1];
                S1 += red[((warpM * 32 + rl1) * 4 + w) * 2 + 0];
                Q1 += red[((warpM * 32 + rl1) * 4 + w) * 2 + 1];
            }
            float mu0 = S0 * (1.0f / D);
            float rs0 = rsqrtf(fmaxf(Q0 * (1.0f / D) - mu0 * mu0, 0.f) + 1e-5f);
            float mu1 = S1 * (1.0f / D);
            float rs1 = rsqrtf(fmaxf(Q1 * (1.0f / D) - mu1 * mu1, 0.f) + 1e-5f);

            int r0 = row0 + warpM * 32 + rl0;
            int r1 = row0 + warpM * 32 + rl1;
#pragma unroll
            for (int nt = 0; nt < 8; nt++) {
                int col = warpN * 64 + nt * 8 + 2 * tig;
                float2 gg = *(const float2*)(gamma + col);
                float2 bb = *(const float2*)(beta + col);
                if (r0 < M) {
                    float t0 = (acc[mt][nt][0] - mu0) * rs0 * gg.x + bb.x;
                    float t1 = (acc[mt][nt][1] - mu0) * rs0 * gg.y + bb.y;
                    float2 o = make_float2(f2tf_f(gelu_exact(t0)), f2tf_f(gelu_exact(t1)));
                    *(float2*)(C + (size_t)r0 * D + col) = o;
                }
                if (r1 < M) {
                    float t2 = (acc[mt][nt][2] - mu1) * rs1 * gg.x + bb.x;
                    float t3 = (acc[mt][nt][3] - mu1) * rs1 * gg.y + bb.y;
                    float2 o = make_float2(f2tf_f(gelu_exact(t2)), f2tf_f(gelu_exact(t3)));
                    *(float2*)(C + (size_t)r1 * D + col) = o;
                }
            }
        }
    } else {
#pragma unroll
        for (int mt = 0; mt < 2; mt++) {
            int r0 = row0 + warpM * 32 + mt * 16 + g;
            int r1 = r0 + 8;
#pragma unroll
            for (int nt = 0; nt < 8; nt++) {
                int col = warpN * 64 + nt * 8 + 2 * tig;
                if (r0 < M) {
                    float2 o = make_float2(acc[mt][nt][0], acc[mt][nt][1]);
                    *(float2*)(C + (size_t)r0 * D + col) = o;
                }
                if (r1 < M) {
                    float2 o = make_float2(acc[mt][nt][2], acc[mt][nt][3]);
                    *(float2*)(C + (size_t)r1 * D + col) = o;
                }
            }
        }
    }
}

// ---------------------------------------------------------------------------
extern "C" void kernel_launch(void* const* d_in, const int* in_sizes, int n_in,
                              void* d_out, int out_size) {
    const float* xin = (const float*)d_in[0];
    const int* srcI  = (const int*)d_in[1];
    const int* dstI  = (const int*)d_in[2];
    const float* ew  = (const float*)d_in[3];
    const float* W1  = (const float*)d_in[4];
    const float* b1  = (const float*)d_in[5];
    const float* g1  = (const float*)d_in[6];
    const float* be1 = (const float*)d_in[7];
    const float* W2  = (const float*)d_in[8];
    const float* b2  = (const float*)d_in[9];
    const float* g2  = (const float*)d_in[10];
    const float* be2 = (const float*)d_in[11];
    const float* Wp  = (const float*)d_in[12];
    const float* bp  = (const float*)d_in[13];

    int n  = in_sizes[0] / D;   // 50000
    int nE = in_sizes[1];       // 800000

    float *agg, *xb, *wt;
    int *cnt;
    int2 *ebuf;
    cudaGetSymbolAddress((void**)&agg, g_agg);
    cudaGetSymbolAddress((void**)&xb, g_x);
    cudaGetSymbolAddress((void**)&wt, g_wt);
    cudaGetSymbolAddress((void**)&cnt, g_cnt);
    cudaGetSymbolAddress((void**)&ebuf, g_ebuf);

    cudaFuncSetAttribute(gemm_fused<true>, cudaFuncAttributeMaxDynamicSharedMemorySize,
                         GEMM_SMEM_BYTES);
    cudaFuncSetAttribute(gemm_fused<false>, cudaFuncAttributeMaxDynamicSharedMemorySize,
                         GEMM_SMEM_BYTES);

    int gmBlocks = (n + 63) / 64;
    int gaBlocks = (n + 7) / 8;
    int eBlocks = (nE + 255) / 256;
    int nBlocks = (n + 255) / 256;

    // ----- One-shot prep: weight rounding + bucketed adjacency build -----
    round_weights<<<(3 * 16384 + 255) / 256, 256>>>(W1, W2, Wp, wt);
    zero_int<<<nBlocks, 256>>>(cnt, n);
    fill_bucket<<<eBlocks, 256>>>(srcI, dstI, ew, cnt, ebuf, nE);

    const float* W1t = wt;
    const float* W2t = wt + D * D;
    const float* Wpt = wt + 2 * D * D;

    // ----- Layer 1 -----
    gather_agg<<<gaBlocks, 256>>>(xin, cnt, ebuf, agg, n);
    gemm_fused<true><<<gmBlocks, 256, GEMM_SMEM_BYTES>>>(agg, W1t, b1, g1, be1, xb, n);

    // ----- Layer 2 -----
    gather_agg<<<gaBlocks, 256>>>(xb, cnt, ebuf, agg, n);
    gemm_fused<true><<<gmBlocks, 256, GEMM_SMEM_BYTES>>>(agg, W2t, b2, g2, be2, xb, n);

    // ----- Output projection -----
    gemm_fused<false><<<gmBlocks, 256, GEMM_SMEM_BYTES>>>(xb, Wpt, bp, nullptr, nullptr,
                                                          (float*)d_out, n);
}